// round 1
// baseline (speedup 1.0000x reference)
#include <cuda_runtime.h>

#define NN 100000
#define EE 400000
#define DD 300
#define D2 600
#define LL 5
#define NV 75            // DD/4 float4 chunks per row
#define BN_EPS 1e-5f

// ---------------- scratch (static device memory; no allocations) ------------
__device__ __align__(128) float g_h  [(size_t)NN * DD];   // 120 MB
__device__ __align__(128) float g_agg[(size_t)NN * DD];   // 120 MB
__device__ __align__(128) float g_hid[(size_t)NN * D2];   // 240 MB
__device__ float g_colsum  [DD];
__device__ float g_colsumsq[DD];

__device__ __forceinline__ void acc4(float4& a, const float4 b) {
    a.x += b.x; a.y += b.y; a.z += b.z; a.w += b.w;
}

// ---------------- atom encoder: h[n] = sum_f atom_tables[f, x[n,f]] --------
__global__ void atom_encoder_kernel(const int* __restrict__ x,
                                    const float* __restrict__ at) {
    int idx = blockIdx.x * blockDim.x + threadIdx.x;
    if (idx >= NN * NV) return;
    int n = idx / NV;
    int d = (idx - n * NV) * 4;
    float4 acc = make_float4(0.f, 0.f, 0.f, 0.f);
#pragma unroll
    for (int f = 0; f < 7; f++) {
        int xi = x[n * 7 + f];
        float4 t = *(const float4*)(at + (size_t)(f * 119 + xi) * DD + d);
        acc4(acc, t);
    }
    *(float4*)(g_h + (size_t)n * DD + d) = acc;
}

// ---------------- agg init: agg[i] = h[i] + selfloop_edge_emb ---------------
// self-loop attr = [4,0,0,0]
__global__ void agg_init_kernel(const float* __restrict__ bond_l) {
    int idx = blockIdx.x * blockDim.x + threadIdx.x;
    if (idx >= NN * NV) return;
    int n = idx / NV;
    int d = (idx - n * NV) * 4;
    float4 v = *(const float4*)(g_h + (size_t)n * DD + d);
    acc4(v, *(const float4*)(bond_l + (0 * 6 + 4) * DD + d));
    acc4(v, *(const float4*)(bond_l + (1 * 6 + 0) * DD + d));
    acc4(v, *(const float4*)(bond_l + (2 * 6 + 0) * DD + d));
    acc4(v, *(const float4*)(bond_l + (3 * 6 + 0) * DD + d));
    *(float4*)(g_agg + (size_t)n * DD + d) = v;
}

// ---------------- edge scatter: agg[dst] += h[src] + bond_emb(edge) --------
__global__ void scatter_edges_kernel(const int* __restrict__ ei,
                                     const int* __restrict__ ea,
                                     const float* __restrict__ bond_l) {
    int idx = blockIdx.x * blockDim.x + threadIdx.x;
    if (idx >= EE * NV) return;
    int e  = idx / NV;
    int d  = (idx - e * NV) * 4;
    int src = ei[e];
    int dst = ei[EE + e];
    float4 v = *(const float4*)(g_h + (size_t)src * DD + d);
#pragma unroll
    for (int f = 0; f < 4; f++) {
        int a = ea[e * 4 + f];
        float4 t = *(const float4*)(bond_l + (size_t)(f * 6 + a) * DD + d);
        acc4(v, t);
    }
    float* p = g_agg + (size_t)dst * DD + d;
    asm volatile("red.global.add.v4.f32 [%0], {%1, %2, %3, %4};"
                 :: "l"(p), "f"(v.x), "f"(v.y), "f"(v.z), "f"(v.w)
                 : "memory");
}

// ---------------- tiled fp32 GEMM: C = A[M,K] @ B[K,N] + bias (opt ReLU) ---
template <bool RELU>
__global__ void gemm_bias_kernel(const float* __restrict__ A,
                                 const float* __restrict__ B,
                                 const float* __restrict__ bias,
                                 float* __restrict__ C,
                                 int M, int Ncols, int K) {
    constexpr int BM = 128, BN = 64, BK = 16;
    __shared__ float As[BK][BM + 4];   // A tile, transposed
    __shared__ float Bs[BK][BN];

    const int tid = threadIdx.x;       // 256 threads
    const int tx = tid & 15;           // 16 col-groups of 4
    const int ty = tid >> 4;           // 16 row-groups of 8
    const int rowBase = blockIdx.y * BM;
    const int colBase = blockIdx.x * BN;

    float acc[8][4];
#pragma unroll
    for (int i = 0; i < 8; i++)
#pragma unroll
        for (int j = 0; j < 4; j++) acc[i][j] = 0.f;

    const int nTiles = (K + BK - 1) / BK;
    for (int kt = 0; kt < nTiles; kt++) {
        const int kBase = kt * BK;
        // load A tile: 512 float4 slots, 2 per thread
#pragma unroll
        for (int i = 0; i < 2; i++) {
            int s = tid + i * 256;
            int m = s >> 2, kv = s & 3;
            int row = rowBase + m, gk = kBase + kv * 4;
            float4 v = make_float4(0.f, 0.f, 0.f, 0.f);
            if (row < M && gk < K)
                v = *(const float4*)(A + (size_t)row * K + gk);
            As[kv * 4 + 0][m] = v.x;
            As[kv * 4 + 1][m] = v.y;
            As[kv * 4 + 2][m] = v.z;
            As[kv * 4 + 3][m] = v.w;
        }
        // load B tile: 256 float4 slots, 1 per thread
        {
            int k = tid >> 4, cv = tid & 15;
            int gk = kBase + k, col = colBase + cv * 4;
            float4 v = make_float4(0.f, 0.f, 0.f, 0.f);
            if (gk < K && col < Ncols)
                v = *(const float4*)(B + (size_t)gk * Ncols + col);
            *(float4*)&Bs[k][cv * 4] = v;
        }
        __syncthreads();
#pragma unroll
        for (int k = 0; k < BK; k++) {
            float4 a0 = *(const float4*)&As[k][ty * 8];
            float4 a1 = *(const float4*)&As[k][ty * 8 + 4];
            float4 b  = *(const float4*)&Bs[k][tx * 4];
            float av[8] = {a0.x, a0.y, a0.z, a0.w, a1.x, a1.y, a1.z, a1.w};
            float bv[4] = {b.x, b.y, b.z, b.w};
#pragma unroll
            for (int i = 0; i < 8; i++)
#pragma unroll
                for (int j = 0; j < 4; j++)
                    acc[i][j] += av[i] * bv[j];
        }
        __syncthreads();
    }

    const int col = colBase + tx * 4;
    if (col < Ncols) {
        float4 bb = *(const float4*)(bias + col);
#pragma unroll
        for (int i = 0; i < 8; i++) {
            int row = rowBase + ty * 8 + i;
            if (row < M) {
                float4 o;
                o.x = acc[i][0] + bb.x;
                o.y = acc[i][1] + bb.y;
                o.z = acc[i][2] + bb.z;
                o.w = acc[i][3] + bb.w;
                if (RELU) {
                    o.x = fmaxf(o.x, 0.f); o.y = fmaxf(o.y, 0.f);
                    o.z = fmaxf(o.z, 0.f); o.w = fmaxf(o.w, 0.f);
                }
                *(float4*)(C + (size_t)row * Ncols + col) = o;
            }
        }
    }
}

// ---------------- batchnorm ------------------------------------------------
__global__ void zero_stats_kernel() {
    int t = threadIdx.x;
    if (t < DD) { g_colsum[t] = 0.f; g_colsumsq[t] = 0.f; }
}

__global__ void bn_stats_kernel(const float* __restrict__ src) {
    int col = threadIdx.x;
    if (col >= DD) return;
    float s = 0.f, s2 = 0.f;
    for (int r = blockIdx.x; r < NN; r += gridDim.x) {
        float v = src[(size_t)r * DD + col];
        s += v; s2 += v * v;
    }
    atomicAdd(&g_colsum[col], s);
    atomicAdd(&g_colsumsq[col], s2);
}

__global__ void bn_apply_kernel(const float* __restrict__ src,
                                const float* __restrict__ gamma,
                                const float* __restrict__ beta,
                                float* __restrict__ dst, int relu) {
    int idx = blockIdx.x * blockDim.x + threadIdx.x;
    if (idx >= NN * NV) return;
    int n = idx / NV;
    int d = (idx - n * NV) * 4;
    float4 v = *(const float4*)(src + (size_t)n * DD + d);
    float o[4] = {v.x, v.y, v.z, v.w};
#pragma unroll
    for (int j = 0; j < 4; j++) {
        int c = d + j;
        float mu  = g_colsum[c]   * (1.f / NN);
        float var = g_colsumsq[c] * (1.f / NN) - mu * mu;
        float inv = rsqrtf(fmaxf(var, 0.f) + BN_EPS);
        float r = (o[j] - mu) * inv * gamma[c] + beta[c];
        if (relu) r = fmaxf(r, 0.f);
        o[j] = r;
    }
    *(float4*)(dst + (size_t)n * DD + d) = make_float4(o[0], o[1], o[2], o[3]);
}

// ---------------- launch ---------------------------------------------------
extern "C" void kernel_launch(void* const* d_in, const int* in_sizes, int n_in,
                              void* d_out, int out_size) {
    const int*   x     = (const int*)d_in[0];
    const int*   ei    = (const int*)d_in[1];
    const int*   ea    = (const int*)d_in[2];
    const float* at    = (const float*)d_in[3];
    const float* bt    = (const float*)d_in[4];
    const float* w1    = (const float*)d_in[5];
    const float* b1    = (const float*)d_in[6];
    const float* w2    = (const float*)d_in[7];
    const float* b2    = (const float*)d_in[8];
    const float* gamma = (const float*)d_in[9];
    const float* beta  = (const float*)d_in[10];
    float* out = (float*)d_out;

    float *p_h, *p_agg, *p_hid;
    cudaGetSymbolAddress((void**)&p_h,   g_h);
    cudaGetSymbolAddress((void**)&p_agg, g_agg);
    cudaGetSymbolAddress((void**)&p_hid, g_hid);

    const int nodeBlocks = (NN * NV + 255) / 256;
    const int edgeBlocks = (EE * NV + 255) / 256;

    atom_encoder_kernel<<<nodeBlocks, 256>>>(x, at);

    for (int l = 0; l < LL; l++) {
        const float* bond_l  = bt + (size_t)l * 4 * 6 * DD;
        const float* w1_l    = w1 + (size_t)l * DD * D2;
        const float* b1_l    = b1 + (size_t)l * D2;
        const float* w2_l    = w2 + (size_t)l * D2 * DD;
        const float* b2_l    = b2 + (size_t)l * DD;
        const float* gamma_l = gamma + (size_t)l * DD;
        const float* beta_l  = beta  + (size_t)l * DD;

        zero_stats_kernel<<<1, 320>>>();
        agg_init_kernel<<<nodeBlocks, 256>>>(bond_l);
        scatter_edges_kernel<<<edgeBlocks, 256>>>(ei, ea, bond_l);

        dim3 g1((D2 + 63) / 64, (NN + 127) / 128);
        gemm_bias_kernel<true><<<g1, 256>>>(p_agg, w1_l, b1_l, p_hid, NN, D2, DD);

        dim3 g2((DD + 63) / 64, (NN + 127) / 128);
        gemm_bias_kernel<false><<<g2, 256>>>(p_hid, w2_l, b2_l, p_agg, NN, DD, D2);

        bn_stats_kernel<<<256, 320>>>(p_agg);

        float* dst = (l == LL - 1) ? out : p_h;
        bn_apply_kernel<<<nodeBlocks, 256>>>(p_agg, gamma_l, beta_l, dst, (l < LL - 1) ? 1 : 0);
    }
}

// round 4
// speedup vs baseline: 1.7924x; 1.7924x over previous
#include <cuda_runtime.h>
#include <cuda_bf16.h>
#include <cstdint>

#define NN 100000
#define EE 400000
#define DD 300
#define D2 600
#define LL 5
#define NV 75
#define BN_EPS 1e-5f

#define K1PAD 320     // GEMM1 K (=DD) padded to mult of 64
#define K2PAD 640     // GEMM2 K (=D2) padded to mult of 64
#define N1PAD 640     // GEMM1 N (=D2) padded to mult of 128
#define N2PAD 384     // GEMM2 N (=DD) padded to mult of 128

// ---------------- scratch (static device memory) ----------------------------
__device__ __align__(128) float g_h  [(size_t)NN * DD];
__device__ __align__(128) float g_agg[(size_t)NN * DD];
__device__ __align__(128) __nv_bfloat16 g_aggH[(size_t)NN * K1PAD];
__device__ __align__(128) __nv_bfloat16 g_aggL[(size_t)NN * K1PAD];
__device__ __align__(128) __nv_bfloat16 g_hidH[(size_t)NN * K2PAD];
__device__ __align__(128) __nv_bfloat16 g_hidL[(size_t)NN * K2PAD];
__device__ __align__(128) __nv_bfloat16 g_w1tH[(size_t)LL * N1PAD * K1PAD];
__device__ __align__(128) __nv_bfloat16 g_w1tL[(size_t)LL * N1PAD * K1PAD];
__device__ __align__(128) __nv_bfloat16 g_w2tH[(size_t)LL * N2PAD * K2PAD];
__device__ __align__(128) __nv_bfloat16 g_w2tL[(size_t)LL * N2PAD * K2PAD];
__device__ float g_colsum  [DD];
__device__ float g_colsumsq[DD];

// ---------------- helpers ---------------------------------------------------
__device__ __forceinline__ uint32_t smem_u32(const void* p) {
    uint32_t a;
    asm("{ .reg .u64 t; cvta.to.shared.u64 t, %1; cvt.u32.u64 %0, t; }" : "=r"(a) : "l"(p));
    return a;
}
#define SW128(off) ((off) ^ (((off) >> 3) & 0x70))
__device__ __forceinline__ void cp_async16(uint32_t dst, const void* src, int sz) {
    asm volatile("cp.async.cg.shared.global [%0], [%1], 16, %2;" :: "r"(dst), "l"(src), "r"(sz) : "memory");
}
__device__ __forceinline__ void acc4(float4& a, const float4 b) {
    a.x += b.x; a.y += b.y; a.z += b.z; a.w += b.w;
}

// ---------------- atom encoder ---------------------------------------------
__global__ void atom_encoder_kernel(const int* __restrict__ x,
                                    const float* __restrict__ at) {
    int idx = blockIdx.x * blockDim.x + threadIdx.x;
    if (idx >= NN * NV) return;
    int n = idx / NV;
    int d = (idx - n * NV) * 4;
    float4 acc = make_float4(0.f, 0.f, 0.f, 0.f);
#pragma unroll
    for (int f = 0; f < 7; f++) {
        int xi = x[n * 7 + f];
        acc4(acc, *(const float4*)(at + (size_t)(f * 119 + xi) * DD + d));
    }
    *(float4*)(g_h + (size_t)n * DD + d) = acc;
}

// ---------------- agg init (self loop) --------------------------------------
__global__ void agg_init_kernel(const float* __restrict__ bond_l) {
    int idx = blockIdx.x * blockDim.x + threadIdx.x;
    if (idx >= NN * NV) return;
    int n = idx / NV;
    int d = (idx - n * NV) * 4;
    float4 v = *(const float4*)(g_h + (size_t)n * DD + d);
    acc4(v, *(const float4*)(bond_l + (0 * 6 + 4) * DD + d));
    acc4(v, *(const float4*)(bond_l + (1 * 6 + 0) * DD + d));
    acc4(v, *(const float4*)(bond_l + (2 * 6 + 0) * DD + d));
    acc4(v, *(const float4*)(bond_l + (3 * 6 + 0) * DD + d));
    *(float4*)(g_agg + (size_t)n * DD + d) = v;
}

// ---------------- edge scatter ----------------------------------------------
__global__ void scatter_edges_kernel(const int* __restrict__ ei,
                                     const int* __restrict__ ea,
                                     const float* __restrict__ bond_l) {
    int idx = blockIdx.x * blockDim.x + threadIdx.x;
    if (idx >= EE * NV) return;
    int e  = idx / NV;
    int d  = (idx - e * NV) * 4;
    int src = ei[e];
    int dst = ei[EE + e];
    float4 v = *(const float4*)(g_h + (size_t)src * DD + d);
#pragma unroll
    for (int f = 0; f < 4; f++) {
        int a = ea[e * 4 + f];
        acc4(v, *(const float4*)(bond_l + (size_t)(f * 6 + a) * DD + d));
    }
    float* p = g_agg + (size_t)dst * DD + d;
    asm volatile("red.global.add.v4.f32 [%0], {%1, %2, %3, %4};"
                 :: "l"(p), "f"(v.x), "f"(v.y), "f"(v.z), "f"(v.w) : "memory");
}

// ---------------- weight transpose + hi/lo split ----------------------------
__global__ void prep_weights_kernel(const float* __restrict__ w1,
                                    const float* __restrict__ w2) {
    const int n1 = LL * N1PAD * K1PAD;
    const int n2 = LL * N2PAD * K2PAD;
    for (int idx = blockIdx.x * blockDim.x + threadIdx.x; idx < n1 + n2;
         idx += gridDim.x * blockDim.x) {
        float v;
        if (idx < n1) {
            int l = idx / (N1PAD * K1PAD);
            int r = idx % (N1PAD * K1PAD);
            int n = r / K1PAD, k = r % K1PAD;
            v = (n < D2 && k < DD) ? w1[(size_t)l * DD * D2 + (size_t)k * D2 + n] : 0.f;
            __nv_bfloat16 hi = __float2bfloat16(v);
            __nv_bfloat16 lo = __float2bfloat16(v - __bfloat162float(hi));
            g_w1tH[idx] = hi; g_w1tL[idx] = lo;
        } else {
            int j = idx - n1;
            int l = j / (N2PAD * K2PAD);
            int r = j % (N2PAD * K2PAD);
            int n = r / K2PAD, k = r % K2PAD;
            v = (n < DD && k < D2) ? w2[(size_t)l * D2 * DD + (size_t)k * DD + n] : 0.f;
            __nv_bfloat16 hi = __float2bfloat16(v);
            __nv_bfloat16 lo = __float2bfloat16(v - __bfloat162float(hi));
            g_w2tH[j] = hi; g_w2tL[j] = lo;
        }
    }
}

// ---------------- decompose agg fp32 -> bf16 hi/lo --------------------------
__global__ void decompose_agg_kernel() {
    int idx = blockIdx.x * blockDim.x + threadIdx.x;
    const int CH = K1PAD / 4;
    if (idx >= NN * CH) return;
    int n = idx / CH;
    int k = (idx - n * CH) * 4;
    float4 v = make_float4(0.f, 0.f, 0.f, 0.f);
    if (k < DD) v = *(const float4*)(g_agg + (size_t)n * DD + k);
    __nv_bfloat16 h4[4], l4[4];
    float vv[4] = {v.x, v.y, v.z, v.w};
#pragma unroll
    for (int j = 0; j < 4; j++) {
        __nv_bfloat16 hi = __float2bfloat16(vv[j]);
        h4[j] = hi;
        l4[j] = __float2bfloat16(vv[j] - __bfloat162float(hi));
    }
    *(uint2*)(g_aggH + (size_t)n * K1PAD + k) = *(uint2*)h4;
    *(uint2*)(g_aggL + (size_t)n * K1PAD + k) = *(uint2*)l4;
}

// ---------------- HMMA bf16x3 GEMM ------------------------------------------
// C[M,Nc] = Ah@Bh^T + Ah@Bl^T + Al@Bh^T  via K-segment loop, fp32 accum.
// B stored N-major (row n holds K values). Block 128x128, 8 warps (32x64 each).
template <bool SPLIT_OUT>
__global__ void __launch_bounds__(256, 2)
gemm_hmma_kernel(const __nv_bfloat16* __restrict__ Ah,
                 const __nv_bfloat16* __restrict__ Al,
                 const __nv_bfloat16* __restrict__ Bh,
                 const __nv_bfloat16* __restrict__ Bl,
                 const float* __restrict__ bias,
                 float* __restrict__ Cf,
                 __nv_bfloat16* __restrict__ Ch,
                 __nv_bfloat16* __restrict__ Cl,
                 int M, int Nc, int Kpad, int Cstride) {
    extern __shared__ __align__(128) char smem[];
    const uint32_t sbase = smem_u32(smem);
    const int tid = threadIdx.x;
    const int lane = tid & 31;
    const int wid = tid >> 5;
    const int wm = wid & 3;          // 4 warps in M
    const int wn = wid >> 2;         // 2 warps in N
    const int rowBase = blockIdx.y * 128;
    const int colBase = blockIdx.x * 128;
    const int stagesPerSeg = Kpad >> 6;
    const int nStages = stagesPerSeg * 3;

    float acc[2][8][4];
#pragma unroll
    for (int i = 0; i < 2; i++)
#pragma unroll
        for (int j = 0; j < 8; j++)
#pragma unroll
            for (int q = 0; q < 4; q++) acc[i][j][q] = 0.f;

    // ---- stage loader (cp.async, one commit group per stage) ----
    auto load_stage = [&](int s) {
        int seg = s / stagesPerSeg;
        int ks = (s - seg * stagesPerSeg) << 6;
        const __nv_bfloat16* As = (seg < 2) ? Ah : Al;
        const __nv_bfloat16* Bs = (seg == 1) ? Bl : Bh;
        uint32_t dA = sbase + (s & 1) * 16384;
        uint32_t dB = sbase + 32768 + (s & 1) * 16384;
#pragma unroll
        for (int i = 0; i < 4; i++) {
            int id = tid + (i << 8);        // 0..1023
            int r = id >> 3, c = id & 7;    // row, 16B chunk
            uint32_t sw = SW128(r * 128 + c * 16);
            int arow = rowBase + r;
            int ok = (arow < M);
            const __nv_bfloat16* ap = As + (size_t)(ok ? arow : 0) * Kpad + ks + c * 8;
            cp_async16(dA + sw, ap, ok ? 16 : 0);
            cp_async16(dB + sw, Bs + (size_t)(colBase + r) * Kpad + ks + c * 8, 16);
        }
        asm volatile("cp.async.commit_group;" ::: "memory");
    };

    load_stage(0);
    for (int s = 0; s < nStages; s++) {
        if (s + 1 < nStages) {
            load_stage(s + 1);
            asm volatile("cp.async.wait_group 1;" ::: "memory");
        } else {
            asm volatile("cp.async.wait_group 0;" ::: "memory");
        }
        __syncthreads();
        uint32_t bA = sbase + (s & 1) * 16384;
        uint32_t bB = sbase + 32768 + (s & 1) * 16384;
#pragma unroll
        for (int k16 = 0; k16 < 4; k16++) {
            const int kB = k16 * 32;        // byte offset of k-chunk
            uint32_t a[2][4], b[4][4];
#pragma unroll
            for (int mf = 0; mf < 2; mf++) {
                int row = wm * 32 + mf * 16 + (lane & 15);
                uint32_t addr = bA + SW128(row * 128 + kB + ((lane >> 4) << 4));
                asm volatile("ldmatrix.sync.aligned.m8n8.x4.shared.b16 {%0,%1,%2,%3}, [%4];"
                    : "=r"(a[mf][0]), "=r"(a[mf][1]), "=r"(a[mf][2]), "=r"(a[mf][3])
                    : "r"(addr));
            }
#pragma unroll
            for (int nq = 0; nq < 4; nq++) {
                int n = wn * 64 + nq * 16 + ((lane >> 4) << 3) + (lane & 7);
                uint32_t addr = bB + SW128(n * 128 + kB + (((lane >> 3) & 1) << 4));
                asm volatile("ldmatrix.sync.aligned.m8n8.x4.shared.b16 {%0,%1,%2,%3}, [%4];"
                    : "=r"(b[nq][0]), "=r"(b[nq][1]), "=r"(b[nq][2]), "=r"(b[nq][3])
                    : "r"(addr));
            }
#pragma unroll
            for (int mf = 0; mf < 2; mf++)
#pragma unroll
                for (int nf = 0; nf < 8; nf++) {
                    const int nq = nf >> 1, h = (nf & 1) << 1;
                    asm volatile(
                        "mma.sync.aligned.m16n8k16.row.col.f32.bf16.bf16.f32 "
                        "{%0,%1,%2,%3}, {%4,%5,%6,%7}, {%8,%9}, {%0,%1,%2,%3};"
                        : "+f"(acc[mf][nf][0]), "+f"(acc[mf][nf][1]),
                          "+f"(acc[mf][nf][2]), "+f"(acc[mf][nf][3])
                        : "r"(a[mf][0]), "r"(a[mf][1]), "r"(a[mf][2]), "r"(a[mf][3]),
                          "r"(b[nq][h]), "r"(b[nq][h + 1]));
                }
        }
        __syncthreads();
    }

    // ---- epilogue ----
    const int r0 = rowBase + wm * 32 + (lane >> 2);
    const int c0 = colBase + wn * 64 + (lane & 3) * 2;
#pragma unroll
    for (int mf = 0; mf < 2; mf++)
#pragma unroll
        for (int nf = 0; nf < 8; nf++) {
            int col = c0 + nf * 8;
#pragma unroll
            for (int hr = 0; hr < 2; hr++) {
                int row = r0 + mf * 16 + hr * 8;
                if (row >= M) continue;
                float v0 = acc[mf][nf][hr * 2 + 0];
                float v1 = acc[mf][nf][hr * 2 + 1];
                if (SPLIT_OUT) {
                    __nv_bfloat16 hv[2], lv[2];
                    if (col < Nc) {
                        v0 = fmaxf(v0 + bias[col], 0.f);
                        v1 = fmaxf(v1 + bias[col + 1], 0.f);
                        hv[0] = __float2bfloat16(v0);
                        lv[0] = __float2bfloat16(v0 - __bfloat162float(hv[0]));
                        hv[1] = __float2bfloat16(v1);
                        lv[1] = __float2bfloat16(v1 - __bfloat162float(hv[1]));
                    } else {
                        hv[0] = hv[1] = __float2bfloat16(0.f);
                        lv[0] = lv[1] = hv[0];
                    }
                    *(uint32_t*)(Ch + (size_t)row * Cstride + col) = *(uint32_t*)hv;
                    *(uint32_t*)(Cl + (size_t)row * Cstride + col) = *(uint32_t*)lv;
                } else {
                    if (col < Nc) {
                        float2 o;
                        o.x = v0 + bias[col];
                        o.y = v1 + bias[col + 1];
                        *(float2*)(Cf + (size_t)row * Cstride + col) = o;
                    }
                }
            }
        }
}

// ---------------- batchnorm ------------------------------------------------
__global__ void zero_stats_kernel() {
    int t = threadIdx.x;
    if (t < DD) { g_colsum[t] = 0.f; g_colsumsq[t] = 0.f; }
}

__global__ void bn_stats_kernel(const float* __restrict__ src) {
    int col = threadIdx.x;
    if (col >= DD) return;
    float s = 0.f, s2 = 0.f;
    for (int r = blockIdx.x; r < NN; r += gridDim.x) {
        float v = src[(size_t)r * DD + col];
        s += v; s2 += v * v;
    }
    atomicAdd(&g_colsum[col], s);
    atomicAdd(&g_colsumsq[col], s2);
}

__global__ void bn_apply_kernel(const float* __restrict__ src,
                                const float* __restrict__ gamma,
                                const float* __restrict__ beta,
                                float* __restrict__ dst, int relu) {
    int idx = blockIdx.x * blockDim.x + threadIdx.x;
    if (idx >= NN * NV) return;
    int n = idx / NV;
    int d = (idx - n * NV) * 4;
    float4 v = *(const float4*)(src + (size_t)n * DD + d);
    float o[4] = {v.x, v.y, v.z, v.w};
#pragma unroll
    for (int j = 0; j < 4; j++) {
        int c = d + j;
        float mu  = g_colsum[c]   * (1.f / NN);
        float var = g_colsumsq[c] * (1.f / NN) - mu * mu;
        float inv = rsqrtf(fmaxf(var, 0.f) + BN_EPS);
        float r = (o[j] - mu) * inv * gamma[c] + beta[c];
        if (relu) r = fmaxf(r, 0.f);
        o[j] = r;
    }
    *(float4*)(dst + (size_t)n * DD + d) = make_float4(o[0], o[1], o[2], o[3]);
}

// ---------------- launch ---------------------------------------------------
extern "C" void kernel_launch(void* const* d_in, const int* in_sizes, int n_in,
                              void* d_out, int out_size) {
    const int*   x     = (const int*)d_in[0];
    const int*   ei    = (const int*)d_in[1];
    const int*   ea    = (const int*)d_in[2];
    const float* at    = (const float*)d_in[3];
    const float* bt    = (const float*)d_in[4];
    const float* w1    = (const float*)d_in[5];
    const float* b1    = (const float*)d_in[6];
    const float* w2    = (const float*)d_in[7];
    const float* b2    = (const float*)d_in[8];
    const float* gamma = (const float*)d_in[9];
    const float* beta  = (const float*)d_in[10];
    float* out = (float*)d_out;

    __nv_bfloat16 *p_aggH, *p_aggL, *p_hidH, *p_hidL, *p_w1tH, *p_w1tL, *p_w2tH, *p_w2tL;
    float *p_agg, *p_h;
    cudaGetSymbolAddress((void**)&p_h,    g_h);
    cudaGetSymbolAddress((void**)&p_agg,  g_agg);
    cudaGetSymbolAddress((void**)&p_aggH, g_aggH);
    cudaGetSymbolAddress((void**)&p_aggL, g_aggL);
    cudaGetSymbolAddress((void**)&p_hidH, g_hidH);
    cudaGetSymbolAddress((void**)&p_hidL, g_hidL);
    cudaGetSymbolAddress((void**)&p_w1tH, g_w1tH);
    cudaGetSymbolAddress((void**)&p_w1tL, g_w1tL);
    cudaGetSymbolAddress((void**)&p_w2tH, g_w2tH);
    cudaGetSymbolAddress((void**)&p_w2tL, g_w2tL);

    const int SMEM_GEMM = 65536;
    cudaFuncSetAttribute(gemm_hmma_kernel<true>,
                         cudaFuncAttributeMaxDynamicSharedMemorySize, SMEM_GEMM);
    cudaFuncSetAttribute(gemm_hmma_kernel<false>,
                         cudaFuncAttributeMaxDynamicSharedMemorySize, SMEM_GEMM);

    const int nodeBlocks = (NN * NV + 255) / 256;
    const int edgeBlocks = (EE * NV + 255) / 256;
    const int rowBlocks  = (NN + 127) / 128;

    atom_encoder_kernel<<<nodeBlocks, 256>>>(x, at);
    prep_weights_kernel<<<2048, 256>>>(w1, w2);

    for (int l = 0; l < LL; l++) {
        const float* bond_l  = bt + (size_t)l * 4 * 6 * DD;
        const float* b1_l    = b1 + (size_t)l * D2;
        const float* b2_l    = b2 + (size_t)l * DD;
        const float* gamma_l = gamma + (size_t)l * DD;
        const float* beta_l  = beta  + (size_t)l * DD;

        zero_stats_kernel<<<1, 320>>>();
        agg_init_kernel<<<nodeBlocks, 256>>>(bond_l);
        scatter_edges_kernel<<<edgeBlocks, 256>>>(ei, ea, bond_l);

        decompose_agg_kernel<<<(NN * (K1PAD / 4) + 255) / 256, 256>>>();

        dim3 g1(N1PAD / 128, rowBlocks);
        gemm_hmma_kernel<true><<<g1, 256, SMEM_GEMM>>>(
            p_aggH, p_aggL,
            p_w1tH + (size_t)l * N1PAD * K1PAD, p_w1tL + (size_t)l * N1PAD * K1PAD,
            b1_l, nullptr, p_hidH, p_hidL, NN, D2, K1PAD, K2PAD);

        dim3 g2(N2PAD / 128, rowBlocks);
        gemm_hmma_kernel<false><<<g2, 256, SMEM_GEMM>>>(
            p_hidH, p_hidL,
            p_w2tH + (size_t)l * N2PAD * K2PAD, p_w2tL + (size_t)l * N2PAD * K2PAD,
            b2_l, p_agg, nullptr, nullptr, NN, DD, K2PAD, DD);

        bn_stats_kernel<<<256, 320>>>(p_agg);

        float* dst = (l == LL - 1) ? out : p_h;
        bn_apply_kernel<<<nodeBlocks, 256>>>(p_agg, gamma_l, beta_l, dst, (l < LL - 1) ? 1 : 0);
    }
}

// round 5
// speedup vs baseline: 2.3033x; 1.2851x over previous
#include <cuda_runtime.h>
#include <cuda_bf16.h>
#include <cstdint>

#define NN 100000
#define EE 400000
#define DD 300
#define D2 600
#define LL 5
#define NV 75
#define BN_EPS 1e-5f

#define K1PAD 320
#define K2PAD 640
#define N1PAD 640
#define N2PAD 320

// ---------------- scratch (static device memory) ----------------------------
__device__ __align__(128) float g_h  [(size_t)NN * DD];
__device__ __align__(128) float g_agg[(size_t)NN * DD];
__device__ __align__(128) __nv_bfloat16 g_aggH[(size_t)NN * K1PAD];
__device__ __align__(128) __nv_bfloat16 g_aggL[(size_t)NN * K1PAD];
__device__ __align__(128) __nv_bfloat16 g_hidH[(size_t)NN * K2PAD];
__device__ __align__(128) __nv_bfloat16 g_hidL[(size_t)NN * K2PAD];
__device__ __align__(128) __nv_bfloat16 g_w1tH[(size_t)LL * N1PAD * K1PAD];
__device__ __align__(128) __nv_bfloat16 g_w1tL[(size_t)LL * N1PAD * K1PAD];
__device__ __align__(128) __nv_bfloat16 g_w2tH[(size_t)LL * N2PAD * K2PAD];
__device__ __align__(128) __nv_bfloat16 g_w2tL[(size_t)LL * N2PAD * K2PAD];
__device__ float g_colsum  [DD];
__device__ float g_colsumsq[DD];

// ---------------- helpers ---------------------------------------------------
__device__ __forceinline__ uint32_t smem_u32(const void* p) {
    uint32_t a;
    asm("{ .reg .u64 t; cvta.to.shared.u64 t, %1; cvt.u32.u64 %0, t; }" : "=r"(a) : "l"(p));
    return a;
}
#define SW64(off) ((off) ^ (((off) >> 3) & 0x30))
__device__ __forceinline__ void cp_async16(uint32_t dst, const void* src, int sz) {
    asm volatile("cp.async.cg.shared.global [%0], [%1], 16, %2;" :: "r"(dst), "l"(src), "r"(sz) : "memory");
}
__device__ __forceinline__ void acc4(float4& a, const float4 b) {
    a.x += b.x; a.y += b.y; a.z += b.z; a.w += b.w;
}
__device__ __forceinline__ void ldsm4(uint32_t* r, uint32_t addr) {
    asm volatile("ldmatrix.sync.aligned.m8n8.x4.shared.b16 {%0,%1,%2,%3}, [%4];"
        : "=r"(r[0]), "=r"(r[1]), "=r"(r[2]), "=r"(r[3]) : "r"(addr));
}
__device__ __forceinline__ void mma16816(float* c, const uint32_t* a, uint32_t b0, uint32_t b1) {
    asm volatile(
        "mma.sync.aligned.m16n8k16.row.col.f32.bf16.bf16.f32 "
        "{%0,%1,%2,%3}, {%4,%5,%6,%7}, {%8,%9}, {%0,%1,%2,%3};"
        : "+f"(c[0]), "+f"(c[1]), "+f"(c[2]), "+f"(c[3])
        : "r"(a[0]), "r"(a[1]), "r"(a[2]), "r"(a[3]), "r"(b0), "r"(b1));
}

// ---------------- atom encoder ---------------------------------------------
__global__ void atom_encoder_kernel(const int* __restrict__ x,
                                    const float* __restrict__ at) {
    int idx = blockIdx.x * blockDim.x + threadIdx.x;
    if (idx >= NN * NV) return;
    int n = idx / NV;
    int d = (idx - n * NV) * 4;
    float4 acc = make_float4(0.f, 0.f, 0.f, 0.f);
#pragma unroll
    for (int f = 0; f < 7; f++) {
        int xi = x[n * 7 + f];
        acc4(acc, *(const float4*)(at + (size_t)(f * 119 + xi) * DD + d));
    }
    *(float4*)(g_h + (size_t)n * DD + d) = acc;
}

// ---------------- agg init (layer 0 only) -----------------------------------
__global__ void agg_init_kernel(const float* __restrict__ bond_l) {
    int idx = blockIdx.x * blockDim.x + threadIdx.x;
    if (idx >= NN * NV) return;
    int n = idx / NV;
    int d = (idx - n * NV) * 4;
    float4 v = *(const float4*)(g_h + (size_t)n * DD + d);
    acc4(v, *(const float4*)(bond_l + (0 * 6 + 4) * DD + d));
    acc4(v, *(const float4*)(bond_l + (1 * 6 + 0) * DD + d));
    acc4(v, *(const float4*)(bond_l + (2 * 6 + 0) * DD + d));
    acc4(v, *(const float4*)(bond_l + (3 * 6 + 0) * DD + d));
    *(float4*)(g_agg + (size_t)n * DD + d) = v;
}

// ---------------- edge scatter ----------------------------------------------
__global__ void scatter_edges_kernel(const int* __restrict__ ei,
                                     const int* __restrict__ ea,
                                     const float* __restrict__ bond_l) {
    int idx = blockIdx.x * blockDim.x + threadIdx.x;
    if (idx >= EE * NV) return;
    int e  = idx / NV;
    int d  = (idx - e * NV) * 4;
    int src = ei[e];
    int dst = ei[EE + e];
    float4 v = *(const float4*)(g_h + (size_t)src * DD + d);
#pragma unroll
    for (int f = 0; f < 4; f++) {
        int a = ea[e * 4 + f];
        acc4(v, *(const float4*)(bond_l + (size_t)(f * 6 + a) * DD + d));
    }
    float* p = g_agg + (size_t)dst * DD + d;
    asm volatile("red.global.add.v4.f32 [%0], {%1, %2, %3, %4};"
                 :: "l"(p), "f"(v.x), "f"(v.y), "f"(v.z), "f"(v.w) : "memory");
}

// ---------------- weight transpose + hi/lo split ----------------------------
__global__ void prep_weights_kernel(const float* __restrict__ w1,
                                    const float* __restrict__ w2) {
    const int n1 = LL * N1PAD * K1PAD;
    const int n2 = LL * N2PAD * K2PAD;
    for (int idx = blockIdx.x * blockDim.x + threadIdx.x; idx < n1 + n2;
         idx += gridDim.x * blockDim.x) {
        float v;
        if (idx < n1) {
            int l = idx / (N1PAD * K1PAD);
            int r = idx % (N1PAD * K1PAD);
            int n = r / K1PAD, k = r % K1PAD;
            v = (n < D2 && k < DD) ? w1[(size_t)l * DD * D2 + (size_t)k * D2 + n] : 0.f;
            __nv_bfloat16 hi = __float2bfloat16(v);
            __nv_bfloat16 lo = __float2bfloat16(v - __bfloat162float(hi));
            g_w1tH[idx] = hi; g_w1tL[idx] = lo;
        } else {
            int j = idx - n1;
            int l = j / (N2PAD * K2PAD);
            int r = j % (N2PAD * K2PAD);
            int n = r / K2PAD, k = r % K2PAD;
            v = (n < DD && k < D2) ? w2[(size_t)l * D2 * DD + (size_t)k * DD + n] : 0.f;
            __nv_bfloat16 hi = __float2bfloat16(v);
            __nv_bfloat16 lo = __float2bfloat16(v - __bfloat162float(hi));
            g_w2tH[j] = hi; g_w2tL[j] = lo;
        }
    }
}

// ---------------- decompose agg fp32 -> bf16 hi/lo --------------------------
__global__ void decompose_agg_kernel() {
    int idx = blockIdx.x * blockDim.x + threadIdx.x;
    const int CH = K1PAD / 4;
    if (idx >= NN * CH) return;
    int n = idx / CH;
    int k = (idx - n * CH) * 4;
    float4 v = make_float4(0.f, 0.f, 0.f, 0.f);
    if (k < DD) v = *(const float4*)(g_agg + (size_t)n * DD + k);
    __nv_bfloat16 h4[4], l4[4];
    float vv[4] = {v.x, v.y, v.z, v.w};
#pragma unroll
    for (int j = 0; j < 4; j++) {
        __nv_bfloat16 hi = __float2bfloat16(vv[j]);
        h4[j] = hi;
        l4[j] = __float2bfloat16(vv[j] - __bfloat162float(hi));
    }
    *(uint2*)(g_aggH + (size_t)n * K1PAD + k) = *(uint2*)h4;
    *(uint2*)(g_aggL + (size_t)n * K1PAD + k) = *(uint2*)l4;
}

// ---------------- merged-K HMMA bf16x3 GEMM ----------------------------------
// C = Ah@Bh^T + Ah@Bl^T + Al@Bh^T, one K pass, all 4 tiles resident per stage.
// Block 128 x BN, 8 warps (4 in M x 2 in N). BK=32, double-buffered cp.async.
template <int BN, bool SPLIT_OUT, bool STATS>
__global__ void __launch_bounds__(256, 2)
gemm_hmma3_kernel(const __nv_bfloat16* __restrict__ Ah,
                  const __nv_bfloat16* __restrict__ Al,
                  const __nv_bfloat16* __restrict__ Bh,
                  const __nv_bfloat16* __restrict__ Bl,
                  const float* __restrict__ bias,
                  float* __restrict__ Cf,
                  __nv_bfloat16* __restrict__ Ch,
                  __nv_bfloat16* __restrict__ Cl,
                  int M, int Nc, int Kpad, int Cstride) {
    constexpr int WN = BN / 2;       // warp N extent
    constexpr int NQ = WN / 16;      // 16-col groups per warp
    constexpr int NF = 2 * NQ;       // 8-col fragments per warp
    constexpr int ASZ = 8192;        // 128 rows x 64B
    constexpr int BSZ = BN * 64;

    extern __shared__ __align__(128) char smem[];
    const uint32_t sbase = smem_u32(smem);
    const uint32_t sAh = sbase;
    const uint32_t sAl = sbase + 2 * ASZ;
    const uint32_t sBh = sbase + 4 * ASZ;
    const uint32_t sBl = sBh + 2 * BSZ;

    const int tid = threadIdx.x;
    const int lane = tid & 31;
    const int wid = tid >> 5;
    const int wm = wid & 3;
    const int wn = wid >> 2;
    const int rowBase = blockIdx.y * 128;
    const int colBase = blockIdx.x * BN;
    const int nStages = Kpad >> 5;

    float acc[2][NF][4];
#pragma unroll
    for (int i = 0; i < 2; i++)
#pragma unroll
        for (int j = 0; j < NF; j++)
#pragma unroll
            for (int q = 0; q < 4; q++) acc[i][j][q] = 0.f;

    auto load_stage = [&](int s) {
        int ks = s << 5;
        uint32_t dAh = sAh + (s & 1) * ASZ;
        uint32_t dAl = sAl + (s & 1) * ASZ;
        uint32_t dBh = sBh + (s & 1) * BSZ;
        uint32_t dBl = sBl + (s & 1) * BSZ;
#pragma unroll
        for (int j = tid; j < 512; j += 256) {
            int r = j >> 2, c = j & 3;
            uint32_t sw = SW64(r * 64 + c * 16);
            int arow = rowBase + r;
            int ok = (arow < M);
            size_t off = (size_t)(ok ? arow : 0) * Kpad + ks + c * 8;
            cp_async16(dAh + sw, Ah + off, ok ? 16 : 0);
            cp_async16(dAl + sw, Al + off, ok ? 16 : 0);
        }
#pragma unroll
        for (int j = tid; j < BN * 4; j += 256) {
            int r = j >> 2, c = j & 3;
            uint32_t sw = SW64(r * 64 + c * 16);
            size_t off = (size_t)(colBase + r) * Kpad + ks + c * 8;
            cp_async16(dBh + sw, Bh + off, 16);
            cp_async16(dBl + sw, Bl + off, 16);
        }
        asm volatile("cp.async.commit_group;" ::: "memory");
    };

    load_stage(0);
    for (int s = 0; s < nStages; s++) {
        if (s + 1 < nStages) {
            load_stage(s + 1);
            asm volatile("cp.async.wait_group 1;" ::: "memory");
        } else {
            asm volatile("cp.async.wait_group 0;" ::: "memory");
        }
        __syncthreads();
        uint32_t bAh = sAh + (s & 1) * ASZ;
        uint32_t bAl = sAl + (s & 1) * ASZ;
        uint32_t bBh = sBh + (s & 1) * BSZ;
        uint32_t bBl = sBl + (s & 1) * BSZ;
#pragma unroll
        for (int k16 = 0; k16 < 2; k16++) {
            const int kB = k16 * 32;
            uint32_t aH[2][4], aL[2][4];
#pragma unroll
            for (int mf = 0; mf < 2; mf++) {
                int row = wm * 32 + mf * 16 + (lane & 15);
                uint32_t boff = SW64(row * 64 + kB + ((lane >> 4) << 4));
                ldsm4(aH[mf], bAh + boff);
                ldsm4(aL[mf], bAl + boff);
            }
#pragma unroll
            for (int nq = 0; nq < NQ; nq++) {
                uint32_t bH[4], bL[4];
                int n = wn * WN + nq * 16 + ((lane >> 4) << 3) + (lane & 7);
                uint32_t boff = SW64(n * 64 + kB + (((lane >> 3) & 1) << 4));
                ldsm4(bH, bBh + boff);
                ldsm4(bL, bBl + boff);
#pragma unroll
                for (int mf = 0; mf < 2; mf++)
#pragma unroll
                    for (int hh = 0; hh < 2; hh++) {
                        const int h = hh << 1;
                        float* c = acc[mf][nq * 2 + hh];
                        mma16816(c, aH[mf], bH[h], bH[h + 1]);
                        mma16816(c, aH[mf], bL[h], bL[h + 1]);
                        mma16816(c, aL[mf], bH[h], bH[h + 1]);
                    }
            }
        }
        __syncthreads();
    }

    // ---- epilogue ----
    const int r0 = rowBase + wm * 32 + (lane >> 2);
    const int c0 = colBase + wn * WN + (lane & 3) * 2;
#pragma unroll
    for (int mf = 0; mf < 2; mf++)
#pragma unroll
        for (int nf = 0; nf < NF; nf++) {
            int col = c0 + nf * 8;
#pragma unroll
            for (int hr = 0; hr < 2; hr++) {
                int row = r0 + mf * 16 + hr * 8;
                float v0 = acc[mf][nf][hr * 2 + 0];
                float v1 = acc[mf][nf][hr * 2 + 1];
                if (SPLIT_OUT) {
                    if (row >= M) continue;
                    __nv_bfloat16 hv[2], lv[2];
                    if (col < Nc) {
                        v0 = fmaxf(v0 + bias[col], 0.f);
                        v1 = fmaxf(v1 + bias[col + 1], 0.f);
                        hv[0] = __float2bfloat16(v0);
                        lv[0] = __float2bfloat16(v0 - __bfloat162float(hv[0]));
                        hv[1] = __float2bfloat16(v1);
                        lv[1] = __float2bfloat16(v1 - __bfloat162float(hv[1]));
                    } else {
                        hv[0] = hv[1] = __float2bfloat16(0.f);
                        lv[0] = lv[1] = hv[0];
                    }
                    *(uint32_t*)(Ch + (size_t)row * Cstride + col) = *(uint32_t*)hv;
                    *(uint32_t*)(Cl + (size_t)row * Cstride + col) = *(uint32_t*)lv;
                } else {
                    if (col < Nc) {
                        v0 += bias[col];
                        v1 += bias[col + 1];
                        acc[mf][nf][hr * 2 + 0] = v0;   // keep post-bias for stats
                        acc[mf][nf][hr * 2 + 1] = v1;
                        if (row < M) {
                            float2 o; o.x = v0; o.y = v1;
                            *(float2*)(Cf + (size_t)row * Cstride + col) = o;
                        }
                    }
                }
            }
        }

    if (STATS) {
#pragma unroll
        for (int nf = 0; nf < NF; nf++)
#pragma unroll
            for (int q = 0; q < 2; q++) {
                int col = c0 + nf * 8 + q;
                float s = 0.f, s2 = 0.f;
                if (col < Nc) {
#pragma unroll
                    for (int mf = 0; mf < 2; mf++)
#pragma unroll
                        for (int hr = 0; hr < 2; hr++) {
                            int row = r0 + mf * 16 + hr * 8;
                            if (row < M) {
                                float v = acc[mf][nf][hr * 2 + q];
                                s += v; s2 += v * v;
                            }
                        }
                }
#pragma unroll
                for (int d = 4; d < 32; d <<= 1) {
                    s  += __shfl_xor_sync(0xffffffffu, s, d);
                    s2 += __shfl_xor_sync(0xffffffffu, s2, d);
                }
                if ((lane >> 2) == 0 && col < Nc) {
                    atomicAdd(&g_colsum[col], s);
                    atomicAdd(&g_colsumsq[col], s2);
                }
            }
    }
}

// ---------------- batchnorm ------------------------------------------------
__global__ void zero_stats_kernel() {
    int t = threadIdx.x;
    if (t < DD) { g_colsum[t] = 0.f; g_colsumsq[t] = 0.f; }
}

// bn apply + (optional) next-layer agg self-loop init, fused.
__global__ void bn_apply_fused_kernel(const float* __restrict__ gamma,
                                      const float* __restrict__ beta,
                                      float* __restrict__ dstH,
                                      const float* __restrict__ bond_next,
                                      int relu) {
    int idx = blockIdx.x * blockDim.x + threadIdx.x;
    if (idx >= NN * NV) return;
    int n = idx / NV;
    int d = (idx - n * NV) * 4;
    float4 v = *(const float4*)(g_agg + (size_t)n * DD + d);
    float o[4] = {v.x, v.y, v.z, v.w};
#pragma unroll
    for (int j = 0; j < 4; j++) {
        int c = d + j;
        float mu  = g_colsum[c]   * (1.f / NN);
        float var = g_colsumsq[c] * (1.f / NN) - mu * mu;
        float inv = rsqrtf(fmaxf(var, 0.f) + BN_EPS);
        float r = (o[j] - mu) * inv * gamma[c] + beta[c];
        if (relu) r = fmaxf(r, 0.f);
        o[j] = r;
    }
    float4 res = make_float4(o[0], o[1], o[2], o[3]);
    *(float4*)(dstH + (size_t)n * DD + d) = res;
    if (bond_next) {
        float4 sl = *(const float4*)(bond_next + (0 * 6 + 4) * DD + d);
        acc4(sl, *(const float4*)(bond_next + (1 * 6 + 0) * DD + d));
        acc4(sl, *(const float4*)(bond_next + (2 * 6 + 0) * DD + d));
        acc4(sl, *(const float4*)(bond_next + (3 * 6 + 0) * DD + d));
        acc4(res, sl);
        *(float4*)(g_agg + (size_t)n * DD + d) = res;
    }
}

// ---------------- launch ---------------------------------------------------
extern "C" void kernel_launch(void* const* d_in, const int* in_sizes, int n_in,
                              void* d_out, int out_size) {
    const int*   x     = (const int*)d_in[0];
    const int*   ei    = (const int*)d_in[1];
    const int*   ea    = (const int*)d_in[2];
    const float* at    = (const float*)d_in[3];
    const float* bt    = (const float*)d_in[4];
    const float* w1    = (const float*)d_in[5];
    const float* b1    = (const float*)d_in[6];
    const float* w2    = (const float*)d_in[7];
    const float* b2    = (const float*)d_in[8];
    const float* gamma = (const float*)d_in[9];
    const float* beta  = (const float*)d_in[10];
    float* out = (float*)d_out;

    __nv_bfloat16 *p_aggH, *p_aggL, *p_hidH, *p_hidL, *p_w1tH, *p_w1tL, *p_w2tH, *p_w2tL;
    float *p_agg, *p_h;
    cudaGetSymbolAddress((void**)&p_h,    g_h);
    cudaGetSymbolAddress((void**)&p_agg,  g_agg);
    cudaGetSymbolAddress((void**)&p_aggH, g_aggH);
    cudaGetSymbolAddress((void**)&p_aggL, g_aggL);
    cudaGetSymbolAddress((void**)&p_hidH, g_hidH);
    cudaGetSymbolAddress((void**)&p_hidL, g_hidL);
    cudaGetSymbolAddress((void**)&p_w1tH, g_w1tH);
    cudaGetSymbolAddress((void**)&p_w1tL, g_w1tL);
    cudaGetSymbolAddress((void**)&p_w2tH, g_w2tH);
    cudaGetSymbolAddress((void**)&p_w2tL, g_w2tL);

    const int SMEM1 = 4 * 8192 + 4 * 128 * 64;   // 64 KB
    const int SMEM2 = 4 * 8192 + 4 * 64 * 64;    // 48 KB
    cudaFuncSetAttribute(gemm_hmma3_kernel<128, true,  false>,
                         cudaFuncAttributeMaxDynamicSharedMemorySize, SMEM1);
    cudaFuncSetAttribute(gemm_hmma3_kernel<64,  false, true>,
                         cudaFuncAttributeMaxDynamicSharedMemorySize, SMEM2);

    const int nodeBlocks = (NN * NV + 255) / 256;
    const int edgeBlocks = (EE * NV + 255) / 256;
    const int rowBlocks  = (NN + 127) / 128;

    atom_encoder_kernel<<<nodeBlocks, 256>>>(x, at);
    prep_weights_kernel<<<2048, 256>>>(w1, w2);

    for (int l = 0; l < LL; l++) {
        const float* bond_l  = bt + (size_t)l * 4 * 6 * DD;
        const float* b1_l    = b1 + (size_t)l * D2;
        const float* b2_l    = b2 + (size_t)l * DD;
        const float* gamma_l = gamma + (size_t)l * DD;
        const float* beta_l  = beta  + (size_t)l * DD;

        if (l == 0) agg_init_kernel<<<nodeBlocks, 256>>>(bond_l);
        scatter_edges_kernel<<<edgeBlocks, 256>>>(ei, ea, bond_l);

        decompose_agg_kernel<<<(NN * (K1PAD / 4) + 255) / 256, 256>>>();

        dim3 g1(N1PAD / 128, rowBlocks);
        gemm_hmma3_kernel<128, true, false><<<g1, 256, SMEM1>>>(
            p_aggH, p_aggL,
            p_w1tH + (size_t)l * N1PAD * K1PAD, p_w1tL + (size_t)l * N1PAD * K1PAD,
            b1_l, nullptr, p_hidH, p_hidL, NN, D2, K1PAD, K2PAD);

        zero_stats_kernel<<<1, 320>>>();

        dim3 g2(N2PAD / 64, rowBlocks);
        gemm_hmma3_kernel<64, false, true><<<g2, 256, SMEM2>>>(
            p_hidH, p_hidL,
            p_w2tH + (size_t)l * N2PAD * K2PAD, p_w2tL + (size_t)l * N2PAD * K2PAD,
            b2_l, p_agg, nullptr, nullptr, NN, DD, K2PAD, DD);

        float* dst = (l == LL - 1) ? out : p_h;
        const float* bond_next = (l < LL - 1) ? bt + (size_t)(l + 1) * 4 * 6 * DD : nullptr;
        bn_apply_fused_kernel<<<nodeBlocks, 256>>>(gamma_l, beta_l, dst, bond_next,
                                                   (l < LL - 1) ? 1 : 0);
    }
}

// round 6
// speedup vs baseline: 2.6051x; 1.1310x over previous
#include <cuda_runtime.h>
#include <cuda_bf16.h>
#include <cstdint>

#define NN 100000
#define EE 400000
#define DD 300
#define D2 600
#define LL 5
#define NV 75
#define BN_EPS 1e-5f

#define K1PAD 320
#define K2PAD 640
#define N1PAD 640
#define N2PAD 320
#define SCAN_BLOCKS ((NN + 1023) / 1024)

// ---------------- scratch (static device memory) ----------------------------
__device__ __align__(128) float g_h  [(size_t)NN * DD];
__device__ __align__(128) float g_agg[(size_t)NN * DD];
__device__ __align__(128) __nv_bfloat16 g_aggH[(size_t)NN * K1PAD];
__device__ __align__(128) __nv_bfloat16 g_aggL[(size_t)NN * K1PAD];
__device__ __align__(128) __nv_bfloat16 g_hidH[(size_t)NN * K2PAD];
__device__ __align__(128) __nv_bfloat16 g_hidL[(size_t)NN * K2PAD];
__device__ __align__(128) __nv_bfloat16 g_w1tH[(size_t)LL * N1PAD * K1PAD];
__device__ __align__(128) __nv_bfloat16 g_w1tL[(size_t)LL * N1PAD * K1PAD];
__device__ __align__(128) __nv_bfloat16 g_w2tH[(size_t)LL * N2PAD * K2PAD];
__device__ __align__(128) __nv_bfloat16 g_w2tL[(size_t)LL * N2PAD * K2PAD];
__device__ float g_colsum  [DD];
__device__ float g_colsumsq[DD];

// CSR build scratch
__device__ int g_deg [NN];
__device__ int g_incl[NN];
__device__ int g_bsum[SCAN_BLOCKS];
__device__ int g_boff[SCAN_BLOCKS];
__device__ int g_rowptr[NN + 1];
__device__ int g_pos [NN];
__device__ int g_esrc[EE];
__device__ uint32_t g_eattr[EE];

// ---------------- helpers ---------------------------------------------------
__device__ __forceinline__ uint32_t smem_u32(const void* p) {
    uint32_t a;
    asm("{ .reg .u64 t; cvta.to.shared.u64 t, %1; cvt.u32.u64 %0, t; }" : "=r"(a) : "l"(p));
    return a;
}
#define SW64(off) ((off) ^ (((off) >> 3) & 0x30))
__device__ __forceinline__ void cp_async16(uint32_t dst, const void* src, int sz) {
    asm volatile("cp.async.cg.shared.global [%0], [%1], 16, %2;" :: "r"(dst), "l"(src), "r"(sz) : "memory");
}
__device__ __forceinline__ void acc4(float4& a, const float4 b) {
    a.x += b.x; a.y += b.y; a.z += b.z; a.w += b.w;
}
__device__ __forceinline__ void ldsm4(uint32_t* r, uint32_t addr) {
    asm volatile("ldmatrix.sync.aligned.m8n8.x4.shared.b16 {%0,%1,%2,%3}, [%4];"
        : "=r"(r[0]), "=r"(r[1]), "=r"(r[2]), "=r"(r[3]) : "r"(addr));
}
__device__ __forceinline__ void mma16816(float* c, const uint32_t* a, uint32_t b0, uint32_t b1) {
    asm volatile(
        "mma.sync.aligned.m16n8k16.row.col.f32.bf16.bf16.f32 "
        "{%0,%1,%2,%3}, {%4,%5,%6,%7}, {%8,%9}, {%0,%1,%2,%3};"
        : "+f"(c[0]), "+f"(c[1]), "+f"(c[2]), "+f"(c[3])
        : "r"(a[0]), "r"(a[1]), "r"(a[2]), "r"(a[3]), "r"(b0), "r"(b1));
}

// ---------------- atom encoder ---------------------------------------------
__global__ void atom_encoder_kernel(const int* __restrict__ x,
                                    const float* __restrict__ at) {
    int idx = blockIdx.x * blockDim.x + threadIdx.x;
    if (idx >= NN * NV) return;
    int n = idx / NV;
    int d = (idx - n * NV) * 4;
    float4 acc = make_float4(0.f, 0.f, 0.f, 0.f);
#pragma unroll
    for (int f = 0; f < 7; f++) {
        int xi = x[n * 7 + f];
        acc4(acc, *(const float4*)(at + (size_t)(f * 119 + xi) * DD + d));
    }
    *(float4*)(g_h + (size_t)n * DD + d) = acc;
}

// ---------------- CSR build --------------------------------------------------
__global__ void zero_deg_kernel() {
    int i = blockIdx.x * blockDim.x + threadIdx.x;
    if (i < NN) g_deg[i] = 0;
}
__global__ void hist_kernel(const int* __restrict__ ei) {
    int e = blockIdx.x * blockDim.x + threadIdx.x;
    if (e < EE) atomicAdd(&g_deg[ei[EE + e]], 1);
}
__global__ void scan1_kernel() {
    __shared__ int s[1024];
    int tid = threadIdx.x;
    int i = blockIdx.x * 1024 + tid;
    int v = (i < NN) ? g_deg[i] : 0;
    s[tid] = v;
    __syncthreads();
#pragma unroll
    for (int o = 1; o < 1024; o <<= 1) {
        int t = (tid >= o) ? s[tid - o] : 0;
        __syncthreads();
        s[tid] += t;
        __syncthreads();
    }
    if (i < NN) g_incl[i] = s[tid];
    if (tid == 1023) g_bsum[blockIdx.x] = s[1023];
}
__global__ void scan2_kernel() {
    if (threadIdx.x == 0) {
        int acc = 0;
        for (int b = 0; b < SCAN_BLOCKS; b++) { g_boff[b] = acc; acc += g_bsum[b]; }
    }
}
__global__ void scan3_kernel() {
    int i = blockIdx.x * blockDim.x + threadIdx.x;
    if (i < NN) {
        int start = g_incl[i] - g_deg[i] + g_boff[i >> 10];
        g_rowptr[i] = start;
        g_pos[i] = start;
    }
    if (i == 0) g_rowptr[NN] = EE;
}
__global__ void fill_kernel(const int* __restrict__ ei, const int* __restrict__ ea) {
    int e = blockIdx.x * blockDim.x + threadIdx.x;
    if (e >= EE) return;
    int dst = ei[EE + e];
    int p = atomicAdd(&g_pos[dst], 1);
    g_esrc[p] = ei[e];
    uint32_t a0 = ea[e * 4 + 0], a1 = ea[e * 4 + 1], a2 = ea[e * 4 + 2], a3 = ea[e * 4 + 3];
    g_eattr[p] = a0 | (a1 << 8) | (a2 << 16) | (a3 << 24);
}

// ---------------- CSR aggregation + direct bf16 hi/lo ------------------------
// agg[n] = h[n] + selfloop_emb + sum_{e in row} (h[src] + bond_emb(e))
__global__ void csr_agg_kernel(const float* __restrict__ bond_l) {
    const int CH = K1PAD / 4;   // 80
    int idx = blockIdx.x * blockDim.x + threadIdx.x;
    if (idx >= NN * CH) return;
    int n = idx / CH;
    int c = idx - n * CH;
    int d = c * 4;
    __nv_bfloat16 h4[4], l4[4];
    if (d < DD) {
        float4 v = *(const float4*)(g_h + (size_t)n * DD + d);
        acc4(v, *(const float4*)(bond_l + (0 * 6 + 4) * DD + d));
        acc4(v, *(const float4*)(bond_l + (1 * 6 + 0) * DD + d));
        acc4(v, *(const float4*)(bond_l + (2 * 6 + 0) * DD + d));
        acc4(v, *(const float4*)(bond_l + (3 * 6 + 0) * DD + d));
        int beg = g_rowptr[n], end = g_rowptr[n + 1];
        for (int e = beg; e < end; e++) {
            int src = g_esrc[e];
            uint32_t at = g_eattr[e];
            acc4(v, *(const float4*)(g_h + (size_t)src * DD + d));
            acc4(v, *(const float4*)(bond_l + (size_t)((at & 0xff)) * DD + d));
            acc4(v, *(const float4*)(bond_l + (size_t)(6 + ((at >> 8) & 0xff)) * DD + d));
            acc4(v, *(const float4*)(bond_l + (size_t)(12 + ((at >> 16) & 0xff)) * DD + d));
            acc4(v, *(const float4*)(bond_l + (size_t)(18 + (at >> 24)) * DD + d));
        }
        float vv[4] = {v.x, v.y, v.z, v.w};
#pragma unroll
        for (int j = 0; j < 4; j++) {
            __nv_bfloat16 hi = __float2bfloat16(vv[j]);
            h4[j] = hi;
            l4[j] = __float2bfloat16(vv[j] - __bfloat162float(hi));
        }
    } else {
        __nv_bfloat16 z = __float2bfloat16(0.f);
#pragma unroll
        for (int j = 0; j < 4; j++) { h4[j] = z; l4[j] = z; }
    }
    *(uint2*)(g_aggH + (size_t)n * K1PAD + d) = *(uint2*)h4;
    *(uint2*)(g_aggL + (size_t)n * K1PAD + d) = *(uint2*)l4;
}

// ---------------- weight transpose + hi/lo split ----------------------------
__global__ void prep_weights_kernel(const float* __restrict__ w1,
                                    const float* __restrict__ w2) {
    const int n1 = LL * N1PAD * K1PAD;
    const int n2 = LL * N2PAD * K2PAD;
    for (int idx = blockIdx.x * blockDim.x + threadIdx.x; idx < n1 + n2;
         idx += gridDim.x * blockDim.x) {
        float v;
        if (idx < n1) {
            int l = idx / (N1PAD * K1PAD);
            int r = idx % (N1PAD * K1PAD);
            int n = r / K1PAD, k = r % K1PAD;
            v = (n < D2 && k < DD) ? w1[(size_t)l * DD * D2 + (size_t)k * D2 + n] : 0.f;
            __nv_bfloat16 hi = __float2bfloat16(v);
            __nv_bfloat16 lo = __float2bfloat16(v - __bfloat162float(hi));
            g_w1tH[idx] = hi; g_w1tL[idx] = lo;
        } else {
            int j = idx - n1;
            int l = j / (N2PAD * K2PAD);
            int r = j % (N2PAD * K2PAD);
            int n = r / K2PAD, k = r % K2PAD;
            v = (n < DD && k < D2) ? w2[(size_t)l * D2 * DD + (size_t)k * DD + n] : 0.f;
            __nv_bfloat16 hi = __float2bfloat16(v);
            __nv_bfloat16 lo = __float2bfloat16(v - __bfloat162float(hi));
            g_w2tH[j] = hi; g_w2tL[j] = lo;
        }
    }
}

// ---------------- merged-K HMMA bf16x3 GEMM ----------------------------------
template <int BN, bool SPLIT_OUT, bool STATS>
__global__ void __launch_bounds__(256, 2)
gemm_hmma3_kernel(const __nv_bfloat16* __restrict__ Ah,
                  const __nv_bfloat16* __restrict__ Al,
                  const __nv_bfloat16* __restrict__ Bh,
                  const __nv_bfloat16* __restrict__ Bl,
                  const float* __restrict__ bias,
                  float* __restrict__ Cf,
                  __nv_bfloat16* __restrict__ Ch,
                  __nv_bfloat16* __restrict__ Cl,
                  int M, int Nc, int Kpad, int Cstride) {
    constexpr int WN = BN / 2;
    constexpr int NQ = WN / 16;
    constexpr int NF = 2 * NQ;
    constexpr int ASZ = 8192;
    constexpr int BSZ = BN * 64;

    extern __shared__ __align__(128) char smem[];
    const uint32_t sbase = smem_u32(smem);
    const uint32_t sAh = sbase;
    const uint32_t sAl = sbase + 2 * ASZ;
    const uint32_t sBh = sbase + 4 * ASZ;
    const uint32_t sBl = sBh + 2 * BSZ;

    const int tid = threadIdx.x;
    const int lane = tid & 31;
    const int wid = tid >> 5;
    const int wm = wid & 3;
    const int wn = wid >> 2;
    const int rowBase = blockIdx.y * 128;
    const int colBase = blockIdx.x * BN;
    const int nStages = Kpad >> 5;

    float acc[2][NF][4];
#pragma unroll
    for (int i = 0; i < 2; i++)
#pragma unroll
        for (int j = 0; j < NF; j++)
#pragma unroll
            for (int q = 0; q < 4; q++) acc[i][j][q] = 0.f;

    auto load_stage = [&](int s) {
        int ks = s << 5;
        uint32_t dAh = sAh + (s & 1) * ASZ;
        uint32_t dAl = sAl + (s & 1) * ASZ;
        uint32_t dBh = sBh + (s & 1) * BSZ;
        uint32_t dBl = sBl + (s & 1) * BSZ;
#pragma unroll
        for (int j = tid; j < 512; j += 256) {
            int r = j >> 2, c = j & 3;
            uint32_t sw = SW64(r * 64 + c * 16);
            int arow = rowBase + r;
            int ok = (arow < M);
            size_t off = (size_t)(ok ? arow : 0) * Kpad + ks + c * 8;
            cp_async16(dAh + sw, Ah + off, ok ? 16 : 0);
            cp_async16(dAl + sw, Al + off, ok ? 16 : 0);
        }
#pragma unroll
        for (int j = tid; j < BN * 4; j += 256) {
            int r = j >> 2, c = j & 3;
            uint32_t sw = SW64(r * 64 + c * 16);
            size_t off = (size_t)(colBase + r) * Kpad + ks + c * 8;
            cp_async16(dBh + sw, Bh + off, 16);
            cp_async16(dBl + sw, Bl + off, 16);
        }
        asm volatile("cp.async.commit_group;" ::: "memory");
    };

    load_stage(0);
    for (int s = 0; s < nStages; s++) {
        if (s + 1 < nStages) {
            load_stage(s + 1);
            asm volatile("cp.async.wait_group 1;" ::: "memory");
        } else {
            asm volatile("cp.async.wait_group 0;" ::: "memory");
        }
        __syncthreads();
        uint32_t bAh = sAh + (s & 1) * ASZ;
        uint32_t bAl = sAl + (s & 1) * ASZ;
        uint32_t bBh = sBh + (s & 1) * BSZ;
        uint32_t bBl = sBl + (s & 1) * BSZ;
#pragma unroll
        for (int k16 = 0; k16 < 2; k16++) {
            const int kB = k16 * 32;
            uint32_t aH[2][4], aL[2][4];
#pragma unroll
            for (int mf = 0; mf < 2; mf++) {
                int row = wm * 32 + mf * 16 + (lane & 15);
                uint32_t boff = SW64(row * 64 + kB + ((lane >> 4) << 4));
                ldsm4(aH[mf], bAh + boff);
                ldsm4(aL[mf], bAl + boff);
            }
#pragma unroll
            for (int nq = 0; nq < NQ; nq++) {
                uint32_t bH[4], bL[4];
                int n = wn * WN + nq * 16 + ((lane >> 4) << 3) + (lane & 7);
                uint32_t boff = SW64(n * 64 + kB + (((lane >> 3) & 1) << 4));
                ldsm4(bH, bBh + boff);
                ldsm4(bL, bBl + boff);
#pragma unroll
                for (int mf = 0; mf < 2; mf++)
#pragma unroll
                    for (int hh = 0; hh < 2; hh++) {
                        const int h = hh << 1;
                        float* c = acc[mf][nq * 2 + hh];
                        mma16816(c, aH[mf], bH[h], bH[h + 1]);
                        mma16816(c, aH[mf], bL[h], bL[h + 1]);
                        mma16816(c, aL[mf], bH[h], bH[h + 1]);
                    }
            }
        }
        __syncthreads();
    }

    const int r0 = rowBase + wm * 32 + (lane >> 2);
    const int c0 = colBase + wn * WN + (lane & 3) * 2;
#pragma unroll
    for (int mf = 0; mf < 2; mf++)
#pragma unroll
        for (int nf = 0; nf < NF; nf++) {
            int col = c0 + nf * 8;
#pragma unroll
            for (int hr = 0; hr < 2; hr++) {
                int row = r0 + mf * 16 + hr * 8;
                float v0 = acc[mf][nf][hr * 2 + 0];
                float v1 = acc[mf][nf][hr * 2 + 1];
                if (SPLIT_OUT) {
                    if (row >= M) continue;
                    __nv_bfloat16 hv[2], lv[2];
                    if (col < Nc) {
                        v0 = fmaxf(v0 + bias[col], 0.f);
                        v1 = fmaxf(v1 + bias[col + 1], 0.f);
                        hv[0] = __float2bfloat16(v0);
                        lv[0] = __float2bfloat16(v0 - __bfloat162float(hv[0]));
                        hv[1] = __float2bfloat16(v1);
                        lv[1] = __float2bfloat16(v1 - __bfloat162float(hv[1]));
                    } else {
                        hv[0] = hv[1] = __float2bfloat16(0.f);
                        lv[0] = lv[1] = hv[0];
                    }
                    *(uint32_t*)(Ch + (size_t)row * Cstride + col) = *(uint32_t*)hv;
                    *(uint32_t*)(Cl + (size_t)row * Cstride + col) = *(uint32_t*)lv;
                } else {
                    if (col < Nc) {
                        v0 += bias[col];
                        v1 += bias[col + 1];
                        acc[mf][nf][hr * 2 + 0] = v0;
                        acc[mf][nf][hr * 2 + 1] = v1;
                        if (row < M) {
                            float2 o; o.x = v0; o.y = v1;
                            *(float2*)(Cf + (size_t)row * Cstride + col) = o;
                        }
                    }
                }
            }
        }

    if (STATS) {
#pragma unroll
        for (int nf = 0; nf < NF; nf++)
#pragma unroll
            for (int q = 0; q < 2; q++) {
                int col = c0 + nf * 8 + q;
                float s = 0.f, s2 = 0.f;
                if (col < Nc) {
#pragma unroll
                    for (int mf = 0; mf < 2; mf++)
#pragma unroll
                        for (int hr = 0; hr < 2; hr++) {
                            int row = r0 + mf * 16 + hr * 8;
                            if (row < M) {
                                float v = acc[mf][nf][hr * 2 + q];
                                s += v; s2 += v * v;
                            }
                        }
                }
#pragma unroll
                for (int d = 4; d < 32; d <<= 1) {
                    s  += __shfl_xor_sync(0xffffffffu, s, d);
                    s2 += __shfl_xor_sync(0xffffffffu, s2, d);
                }
                if ((lane >> 2) == 0 && col < Nc) {
                    atomicAdd(&g_colsum[col], s);
                    atomicAdd(&g_colsumsq[col], s2);
                }
            }
    }
}

// ---------------- batchnorm ------------------------------------------------
__global__ void zero_stats_kernel() {
    int t = threadIdx.x;
    if (t < DD) { g_colsum[t] = 0.f; g_colsumsq[t] = 0.f; }
}

__global__ void bn_apply_kernel(const float* __restrict__ gamma,
                                const float* __restrict__ beta,
                                float* __restrict__ dst, int relu) {
    int idx = blockIdx.x * blockDim.x + threadIdx.x;
    if (idx >= NN * NV) return;
    int n = idx / NV;
    int d = (idx - n * NV) * 4;
    float4 v = *(const float4*)(g_agg + (size_t)n * DD + d);
    float o[4] = {v.x, v.y, v.z, v.w};
#pragma unroll
    for (int j = 0; j < 4; j++) {
        int c = d + j;
        float mu  = g_colsum[c]   * (1.f / NN);
        float var = g_colsumsq[c] * (1.f / NN) - mu * mu;
        float inv = rsqrtf(fmaxf(var, 0.f) + BN_EPS);
        float r = (o[j] - mu) * inv * gamma[c] + beta[c];
        if (relu) r = fmaxf(r, 0.f);
        o[j] = r;
    }
    *(float4*)(dst + (size_t)n * DD + d) = make_float4(o[0], o[1], o[2], o[3]);
}

// ---------------- launch ---------------------------------------------------
extern "C" void kernel_launch(void* const* d_in, const int* in_sizes, int n_in,
                              void* d_out, int out_size) {
    const int*   x     = (const int*)d_in[0];
    const int*   ei    = (const int*)d_in[1];
    const int*   ea    = (const int*)d_in[2];
    const float* at    = (const float*)d_in[3];
    const float* bt    = (const float*)d_in[4];
    const float* w1    = (const float*)d_in[5];
    const float* b1    = (const float*)d_in[6];
    const float* w2    = (const float*)d_in[7];
    const float* b2    = (const float*)d_in[8];
    const float* gamma = (const float*)d_in[9];
    const float* beta  = (const float*)d_in[10];
    float* out = (float*)d_out;

    __nv_bfloat16 *p_aggH, *p_aggL, *p_hidH, *p_hidL, *p_w1tH, *p_w1tL, *p_w2tH, *p_w2tL;
    float *p_agg, *p_h;
    cudaGetSymbolAddress((void**)&p_h,    g_h);
    cudaGetSymbolAddress((void**)&p_agg,  g_agg);
    cudaGetSymbolAddress((void**)&p_aggH, g_aggH);
    cudaGetSymbolAddress((void**)&p_aggL, g_aggL);
    cudaGetSymbolAddress((void**)&p_hidH, g_hidH);
    cudaGetSymbolAddress((void**)&p_hidL, g_hidL);
    cudaGetSymbolAddress((void**)&p_w1tH, g_w1tH);
    cudaGetSymbolAddress((void**)&p_w1tL, g_w1tL);
    cudaGetSymbolAddress((void**)&p_w2tH, g_w2tH);
    cudaGetSymbolAddress((void**)&p_w2tL, g_w2tL);

    const int SMEM1 = 4 * 8192 + 4 * 128 * 64;   // 64 KB
    const int SMEM2 = 4 * 8192 + 4 * 64 * 64;    // 48 KB
    cudaFuncSetAttribute(gemm_hmma3_kernel<128, true,  false>,
                         cudaFuncAttributeMaxDynamicSharedMemorySize, SMEM1);
    cudaFuncSetAttribute(gemm_hmma3_kernel<64,  false, true>,
                         cudaFuncAttributeMaxDynamicSharedMemorySize, SMEM2);

    const int nodeBlocks = (NN * NV + 255) / 256;
    const int aggBlocks  = (NN * (K1PAD / 4) + 255) / 256;
    const int edgeBlocks = (EE + 255) / 256;
    const int nBlocks    = (NN + 255) / 256;
    const int rowBlocks  = (NN + 127) / 128;

    atom_encoder_kernel<<<nodeBlocks, 256>>>(x, at);
    prep_weights_kernel<<<2048, 256>>>(w1, w2);

    // CSR build (edge structure is launch-invariant; reused across layers)
    zero_deg_kernel<<<nBlocks, 256>>>();
    hist_kernel<<<edgeBlocks, 256>>>(ei);
    scan1_kernel<<<SCAN_BLOCKS, 1024>>>();
    scan2_kernel<<<1, 32>>>();
    scan3_kernel<<<nBlocks, 256>>>();
    fill_kernel<<<edgeBlocks, 256>>>(ei, ea);

    for (int l = 0; l < LL; l++) {
        const float* bond_l  = bt + (size_t)l * 4 * 6 * DD;
        const float* b1_l    = b1 + (size_t)l * D2;
        const float* b2_l    = b2 + (size_t)l * DD;
        const float* gamma_l = gamma + (size_t)l * DD;
        const float* beta_l  = beta  + (size_t)l * DD;

        csr_agg_kernel<<<aggBlocks, 256>>>(bond_l);

        dim3 g1(N1PAD / 128, rowBlocks);
        gemm_hmma3_kernel<128, true, false><<<g1, 256, SMEM1>>>(
            p_aggH, p_aggL,
            p_w1tH + (size_t)l * N1PAD * K1PAD, p_w1tL + (size_t)l * N1PAD * K1PAD,
            b1_l, nullptr, p_hidH, p_hidL, NN, D2, K1PAD, K2PAD);

        zero_stats_kernel<<<1, 320>>>();

        dim3 g2(N2PAD / 64, rowBlocks);
        gemm_hmma3_kernel<64, false, true><<<g2, 256, SMEM2>>>(
            p_hidH, p_hidL,
            p_w2tH + (size_t)l * N2PAD * K2PAD, p_w2tL + (size_t)l * N2PAD * K2PAD,
            b2_l, p_agg, nullptr, nullptr, NN, DD, K2PAD, DD);

        float* dst = (l == LL - 1) ? out : p_h;
        bn_apply_kernel<<<nodeBlocks, 256>>>(gamma_l, beta_l, dst, (l < LL - 1) ? 1 : 0);
    }
}